// round 11
// baseline (speedup 1.0000x reference)
#include <cuda_runtime.h>
#include <cuda_fp16.h>
#include <cstdint>

#define HD   128
#define NPC  64            // nodes per CTA (two independent halves of 32)
#define NT   512
#define DEG  16
#define NNODES 16384

// Fragment-major weights: [mat(2: 0=ih,1=hh)][prec(2: 0=hi,1=lo)][mt(32)][kt(8)][lane(32)][8 halves]
// mt = wh*4 + t4 ; global row = t4*128 + wh*16 + r_local.
__device__ __align__(16) __half g_Wfrag[2][2][32][8][32][8];

__global__ void prep_w(const float* __restrict__ Wih, const float* __restrict__ Whh) {
    int idx = blockIdx.x * blockDim.x + threadIdx.x;      // 16384 threads
    if (idx >= 2 * 32 * 8 * 32) return;
    int lane = idx & 31;
    int kt   = (idx >> 5) & 7;
    int mt   = (idx >> 8) & 31;
    int mat  = idx >> 13;
    const float* W = mat ? Whh : Wih;
    int wh = mt >> 2, t4 = mt & 3;
    int g = lane >> 2, tig = lane & 3;
    int rb = t4 * 128 + wh * 16;
    int kb = kt * 16 + tig * 2;
    int rows[8] = {g, g, g + 8, g + 8, g, g, g + 8, g + 8};
    int cols[8] = {kb, kb + 1, kb, kb + 1, kb + 8, kb + 9, kb + 8, kb + 9};
    __half hi[8], lo[8];
#pragma unroll
    for (int i = 0; i < 8; ++i) {
        float v = W[(rb + rows[i]) * HD + cols[i]];
        __half h = __float2half_rn(v);
        hi[i] = h;
        lo[i] = __float2half_rn(v - __half2float(h));
    }
    *(uint4*)&g_Wfrag[mat][0][mt][kt][lane][0] = *(uint4*)hi;
    *(uint4*)&g_Wfrag[mat][1][mt][kt][lane][0] = *(uint4*)lo;
}

// ---- hardware tanh (MUFU.TANH), single-op activations ----
__device__ __forceinline__ float tanh_hw(float x) {
    float y;
    asm("tanh.approx.f32 %0, %1;" : "=f"(y) : "f"(x));
    return y;
}
__device__ __forceinline__ float sigf(float v) {
    return fmaf(0.5f, tanh_hw(0.5f * v), 0.5f);
}

#define MMA(acc, a, b0, b1)                                              \
    asm volatile("mma.sync.aligned.m16n8k16.row.col.f32.f16.f16.f32 "    \
                 "{%0,%1,%2,%3}, {%4,%5,%6,%7}, {%8,%9}, {%0,%1,%2,%3};" \
                 : "+f"((acc)[0]), "+f"((acc)[1]), "+f"((acc)[2]), "+f"((acc)[3]) \
                 : "r"((a).x), "r"((a).y), "r"((a).z), "r"((a).w), "r"(b0), "r"(b1))

// Per-half slabs: HI[buf(2)][src(2)][kpair(64)][ROWW], same for LO.
// ROWW = 32 nodes + 8 pad -> LDS pattern tig*40+g covers banks 0..31 conflict-free.
#define ROWW 40
#define SLAB (2 * 64 * ROWW)     // words per buffer (both srcs) = 5120
#define HALFW (4 * SLAB)         // HI 2 bufs + LO 2 bufs = 20480 words per half
#define SMEM_WORDS (2 * HALFW)   // 40960 words = 160 KB

__global__ __launch_bounds__(NT, 1)
void lstm_mma_kernel(const float* __restrict__ x,
                     const float* __restrict__ bih,
                     const float* __restrict__ bhh,
                     float* __restrict__ out) {
    extern __shared__ uint32_t sm[];

    const int tid = threadIdx.x, lane = tid & 31, w = tid >> 5;
    const int half = w >> 3, wh = w & 7;
    const int g = lane >> 2, tig = lane & 3;
    const int n0 = blockIdx.x * NPC + half * 32;   // first node of this half

    uint32_t* HI = sm + half * HALFW;              // [buf][src][64][ROWW]
    uint32_t* LO = HI + 2 * SLAB;

    // per-thread bias regs [gate-type][row-half]
    float bias[4][2];
#pragma unroll
    for (int t = 0; t < 4; ++t)
#pragma unroll
        for (int hf = 0; hf < 2; ++hf) {
            int d = t * 128 + wh * 16 + hf * 8 + g;
            bias[t][hf] = bih[d] + bhh[d];
        }

    float cst[4][2][2];
#pragma unroll
    for (int a = 0; a < 4; ++a)
        for (int b = 0; b < 2; ++b)
            for (int c = 0; c < 2; ++c) cst[a][b][c] = 0.0f;

    // ---- convert x(0) into buf 0, src 0 (warp w: dims wh*16..+16, node = lane) ----
    {
        const float* xr = x + ((size_t)(n0 + lane) * DEG + 0) * HD + wh * 16;
#pragma unroll
        for (int i = 0; i < 8; ++i) {
            float2 v = *(const float2*)(xr + 2 * i);
            float v0 = (v.x == v.x) ? v.x : 0.0f;
            float v1 = (v.y == v.y) ? v.y : 0.0f;
            __half2 h2 = __floats2half2_rn(v0, v1);
            __half2 l2 = __floats2half2_rn(v0 - __half2float(__low2half(h2)),
                                           v1 - __half2float(__high2half(h2)));
            int kp = wh * 8 + i;
            HI[kp * ROWW + lane] = *(uint32_t*)&h2;
            LO[kp * ROWW + lane] = *(uint32_t*)&l2;
        }
    }
    __syncthreads();   // one full sync; afterwards halves run on their own barriers

    // accumulators pre-initialized with bias
    float acc[4][4][4];
#pragma unroll
    for (int t = 0; t < 4; ++t)
#pragma unroll
        for (int nt = 0; nt < 4; ++nt)
#pragma unroll
            for (int ri = 0; ri < 4; ++ri) acc[t][nt][ri] = bias[t][ri >> 1];

#pragma unroll 1
    for (int u = 0; u < DEG; ++u) {
        const int rb = (u & 1) * SLAB;          // GEMM reads this buffer
        const int wb = ((u + 1) & 1) * SLAB;    // epi/convert write this buffer

        // ---- GEMM: src 0 = x (Wih), src 1 = h (Whh) ----
#pragma unroll 1
        for (int src = 0; src < 2; ++src) {
            if (src == 1 && u == 0) break;
#pragma unroll 1
            for (int kt = 0; kt < 8; ++kt) {
                const int bidx = rb + (src * 64 + kt * 8 + tig) * ROWW + g;
                uint4 af[4];
#pragma unroll
                for (int t = 0; t < 4; ++t)
                    af[t] = __ldg((const uint4*)&g_Wfrag[src][0][wh * 4 + t][kt][lane][0]);
#pragma unroll
                for (int nt = 0; nt < 4; ++nt) {
                    uint32_t bh0 = HI[bidx + nt * 8];
                    uint32_t bh1 = HI[bidx + 4 * ROWW + nt * 8];
                    uint32_t bl0 = LO[bidx + nt * 8];
                    uint32_t bl1 = LO[bidx + 4 * ROWW + nt * 8];
#pragma unroll
                    for (int t = 0; t < 4; ++t) MMA(acc[t][nt], af[t], bh0, bh1);
#pragma unroll
                    for (int t = 0; t < 4; ++t) MMA(acc[t][nt], af[t], bl0, bl1);
                }
#pragma unroll
                for (int t = 0; t < 4; ++t)
                    af[t] = __ldg((const uint4*)&g_Wfrag[src][1][wh * 4 + t][kt][lane][0]);
#pragma unroll
                for (int nt = 0; nt < 4; ++nt) {
                    uint32_t bh0 = HI[bidx + nt * 8];
                    uint32_t bh1 = HI[bidx + 4 * ROWW + nt * 8];
#pragma unroll
                    for (int t = 0; t < 4; ++t) MMA(acc[t][nt], af[t], bh0, bh1);
                }
            }
        }

        // ---- convert x(u+1) -> wb src0 (LDG latency hides under epilogue math) ----
        if (u < DEG - 1) {
            const float* xr = x + ((size_t)(n0 + lane) * DEG + (u + 1)) * HD + wh * 16;
#pragma unroll
            for (int i = 0; i < 8; ++i) {
                float2 v = *(const float2*)(xr + 2 * i);
                float v0 = (v.x == v.x) ? v.x : 0.0f;
                float v1 = (v.y == v.y) ? v.y : 0.0f;
                __half2 h2 = __floats2half2_rn(v0, v1);
                __half2 l2 = __floats2half2_rn(v0 - __half2float(__low2half(h2)),
                                               v1 - __half2float(__high2half(h2)));
                int kp = wh * 8 + i;
                HI[wb + kp * ROWW + lane] = *(uint32_t*)&h2;
                LO[wb + kp * ROWW + lane] = *(uint32_t*)&l2;
            }
        }

        // ---- epilogue: cell update (bias already inside acc); reset acc to bias ----
#pragma unroll
        for (int nt = 0; nt < 4; ++nt)
#pragma unroll
            for (int hf = 0; hf < 2; ++hf)
#pragma unroll
                for (int cb = 0; cb < 2; ++cb) {
                    const int ri = hf * 2 + cb;
                    float gi = acc[0][nt][ri];
                    float gf = acc[1][nt][ri];
                    float gg = acc[2][nt][ri];
                    float go = acc[3][nt][ri];
                    acc[0][nt][ri] = bias[0][hf];
                    acc[1][nt][ri] = bias[1][hf];
                    acc[2][nt][ri] = bias[2][hf];
                    acc[3][nt][ri] = bias[3][hf];
                    float iv = sigf(gi), fv = sigf(gf), ov = sigf(go);
                    float gv = tanh_hw(gg);
                    float cn = fv * cst[nt][hf][cb] + iv * gv;
                    cst[nt][hf][cb] = cn;
                    float hv = ov * tanh_hw(cn);
                    const int d = wh * 16 + hf * 8 + g;
                    const int n = nt * 8 + tig * 2 + cb;        // local node 0..31
                    if (u < DEG - 1) {
                        __half hh = __float2half_rn(hv);
                        __half hl = __float2half_rn(hv - __half2float(hh));
                        const int kidx = wb + (64 + (d >> 1)) * ROWW + n;
                        ((__half*)&HI[kidx])[d & 1] = hh;
                        ((__half*)&LO[kidx])[d & 1] = hl;
                    } else {
                        out[(size_t)(n0 + n) * HD + d] = hv;
                    }
                }

        // per-half barrier: halves drift independently -> tensor/MUFU phases overlap
        asm volatile("bar.sync %0, 256;" :: "r"(half + 1) : "memory");
    }
}

extern "C" void kernel_launch(void* const* d_in, const int* in_sizes, int n_in,
                              void* d_out, int out_size) {
    // metadata order: x, index, W_ih, W_hh, b_ih, b_hh, dim_size
    const float* x   = (const float*)d_in[0];
    const float* Wih = (const float*)d_in[2];
    const float* Whh = (const float*)d_in[3];
    const float* bih = (const float*)d_in[4];
    const float* bhh = (const float*)d_in[5];
    float* out = (float*)d_out;

    prep_w<<<64, 256>>>(Wih, Whh);

    const int smem_bytes = SMEM_WORDS * (int)sizeof(uint32_t);   // 163840
    static bool attr_set = false;
    if (!attr_set) {
        cudaFuncSetAttribute(lstm_mma_kernel,
                             cudaFuncAttributeMaxDynamicSharedMemorySize, smem_bytes);
        attr_set = true;
    }
    lstm_mma_kernel<<<NNODES / NPC, NT, smem_bytes>>>(x, bih, bhh, out);
}

// round 15
// speedup vs baseline: 1.5353x; 1.5353x over previous
#include <cuda_runtime.h>
#include <cuda_fp16.h>
#include <cstdint>

#define HD   128
#define NPC  64            // nodes per CTA (two independent halves of 32)
#define NT   512
#define DEG  16
#define NNODES 16384

// Fragment-major weights: [mat(2: 0=ih,1=hh)][prec(2: 0=hi,1=lo)][mt(32)][kt(8)][lane(32)][8 halves]
// mt = wh*4 + t4 ; global row = t4*128 + wh*16 + r_local.
__device__ __align__(16) __half g_Wfrag[2][2][32][8][32][8];

__global__ void prep_w(const float* __restrict__ Wih, const float* __restrict__ Whh) {
    int idx = blockIdx.x * blockDim.x + threadIdx.x;      // 16384 threads
    if (idx >= 2 * 32 * 8 * 32) return;
    int lane = idx & 31;
    int kt   = (idx >> 5) & 7;
    int mt   = (idx >> 8) & 31;
    int mat  = idx >> 13;
    const float* W = mat ? Whh : Wih;
    int wh = mt >> 2, t4 = mt & 3;
    int g = lane >> 2, tig = lane & 3;
    int rb = t4 * 128 + wh * 16;
    int kb = kt * 16 + tig * 2;
    int rows[8] = {g, g, g + 8, g + 8, g, g, g + 8, g + 8};
    int cols[8] = {kb, kb + 1, kb, kb + 1, kb + 8, kb + 9, kb + 8, kb + 9};
    __half hi[8], lo[8];
#pragma unroll
    for (int i = 0; i < 8; ++i) {
        float v = W[(rb + rows[i]) * HD + cols[i]];
        __half h = __float2half_rn(v);
        hi[i] = h;
        lo[i] = __float2half_rn(v - __half2float(h));
    }
    *(uint4*)&g_Wfrag[mat][0][mt][kt][lane][0] = *(uint4*)hi;
    *(uint4*)&g_Wfrag[mat][1][mt][kt][lane][0] = *(uint4*)lo;
}

// ---- hardware tanh (MUFU.TANH), single-op activations ----
__device__ __forceinline__ float tanh_hw(float x) {
    float y;
    asm("tanh.approx.f32 %0, %1;" : "=f"(y) : "f"(x));
    return y;
}
__device__ __forceinline__ float sigf(float v) {
    return fmaf(0.5f, tanh_hw(0.5f * v), 0.5f);
}

#define MMA(acc, a, b0, b1)                                              \
    asm volatile("mma.sync.aligned.m16n8k16.row.col.f32.f16.f16.f32 "    \
                 "{%0,%1,%2,%3}, {%4,%5,%6,%7}, {%8,%9}, {%0,%1,%2,%3};" \
                 : "+f"((acc)[0]), "+f"((acc)[1]), "+f"((acc)[2]), "+f"((acc)[3]) \
                 : "r"((a).x), "r"((a).y), "r"((a).z), "r"((a).w), "r"(b0), "r"(b1))

// Per-half slabs: HI[buf(2)][src(2)][kpair(64)][ROWW], same for LO.
// ROWW = 32 nodes + 8 pad -> LDS pattern tig*40+g covers banks 0..31 conflict-free.
#define ROWW 40
#define SLAB (2 * 64 * ROWW)     // words per buffer (both srcs) = 5120
#define HALFW (4 * SLAB)         // HI 2 bufs + LO 2 bufs = 20480 words per half
#define SMEM_WORDS (2 * HALFW)   // 40960 words = 160 KB

__global__ __launch_bounds__(NT, 1)
void lstm_mma_kernel(const float* __restrict__ x,
                     const float* __restrict__ bih,
                     const float* __restrict__ bhh,
                     float* __restrict__ out) {
    extern __shared__ uint32_t sm[];

    const int tid = threadIdx.x, lane = tid & 31, w = tid >> 5;
    const int half = w >> 3, wh = w & 7;
    const int g = lane >> 2, tig = lane & 3;
    const int n0 = blockIdx.x * NPC + half * 32;   // first node of this half

    uint32_t* HI = sm + half * HALFW;              // [buf][src][64][ROWW]
    uint32_t* LO = HI + 2 * SLAB;

    // per-thread bias regs [gate-type][row-half]
    float bias[4][2];
#pragma unroll
    for (int t = 0; t < 4; ++t)
#pragma unroll
        for (int hf = 0; hf < 2; ++hf) {
            int d = t * 128 + wh * 16 + hf * 8 + g;
            bias[t][hf] = bih[d] + bhh[d];
        }

    float cst[4][2][2];
#pragma unroll
    for (int a = 0; a < 4; ++a)
        for (int b = 0; b < 2; ++b)
            for (int c = 0; c < 2; ++c) cst[a][b][c] = 0.0f;

    // ---- convert x(0) into buf 0, src 0 (warp w: dims wh*16..+16, node = lane) ----
    {
        const float* xr = x + ((size_t)(n0 + lane) * DEG + 0) * HD + wh * 16;
#pragma unroll
        for (int i = 0; i < 8; ++i) {
            float2 v = *(const float2*)(xr + 2 * i);
            float v0 = (v.x == v.x) ? v.x : 0.0f;
            float v1 = (v.y == v.y) ? v.y : 0.0f;
            __half2 h2 = __floats2half2_rn(v0, v1);
            __half2 l2 = __floats2half2_rn(v0 - __half2float(__low2half(h2)),
                                           v1 - __half2float(__high2half(h2)));
            int kp = wh * 8 + i;
            HI[kp * ROWW + lane] = *(uint32_t*)&h2;
            LO[kp * ROWW + lane] = *(uint32_t*)&l2;
        }
    }
    __syncthreads();   // one full sync; afterwards halves run on their own barriers

    // accumulators pre-initialized with bias
    float acc[4][4][4];
#pragma unroll
    for (int t = 0; t < 4; ++t)
#pragma unroll
        for (int nt = 0; nt < 4; ++nt)
#pragma unroll
            for (int ri = 0; ri < 4; ++ri) acc[t][nt][ri] = bias[t][ri >> 1];

#pragma unroll 1
    for (int u = 0; u < DEG; ++u) {
        const int rb = (u & 1) * SLAB;          // GEMM reads this buffer
        const int wb = ((u + 1) & 1) * SLAB;    // epi/convert write this buffer

        // ---- GEMM: src 0 = x (Wih), src 1 = h (Whh) ----
#pragma unroll 1
        for (int src = 0; src < 2; ++src) {
            if (src == 1 && u == 0) break;
#pragma unroll 1
            for (int kt = 0; kt < 8; ++kt) {
                const int bidx = rb + (src * 64 + kt * 8 + tig) * ROWW + g;
                uint4 af[4];
#pragma unroll
                for (int t = 0; t < 4; ++t)
                    af[t] = __ldg((const uint4*)&g_Wfrag[src][0][wh * 4 + t][kt][lane][0]);
#pragma unroll
                for (int nt = 0; nt < 4; ++nt) {
                    uint32_t bh0 = HI[bidx + nt * 8];
                    uint32_t bh1 = HI[bidx + 4 * ROWW + nt * 8];
                    uint32_t bl0 = LO[bidx + nt * 8];
                    uint32_t bl1 = LO[bidx + 4 * ROWW + nt * 8];
#pragma unroll
                    for (int t = 0; t < 4; ++t) MMA(acc[t][nt], af[t], bh0, bh1);
#pragma unroll
                    for (int t = 0; t < 4; ++t) MMA(acc[t][nt], af[t], bl0, bl1);
                }
#pragma unroll
                for (int t = 0; t < 4; ++t)
                    af[t] = __ldg((const uint4*)&g_Wfrag[src][1][wh * 4 + t][kt][lane][0]);
#pragma unroll
                for (int nt = 0; nt < 4; ++nt) {
                    uint32_t bh0 = HI[bidx + nt * 8];
                    uint32_t bh1 = HI[bidx + 4 * ROWW + nt * 8];
#pragma unroll
                    for (int t = 0; t < 4; ++t) MMA(acc[t][nt], af[t], bh0, bh1);
                }
            }
        }

        // ---- epilogue: cell update (bias already inside acc); reset acc to bias ----
#pragma unroll
        for (int nt = 0; nt < 4; ++nt)
#pragma unroll
            for (int hf = 0; hf < 2; ++hf)
#pragma unroll
                for (int cb = 0; cb < 2; ++cb) {
                    const int ri = hf * 2 + cb;
                    float gi = acc[0][nt][ri];
                    float gf = acc[1][nt][ri];
                    float gg = acc[2][nt][ri];
                    float go = acc[3][nt][ri];
                    acc[0][nt][ri] = bias[0][hf];
                    acc[1][nt][ri] = bias[1][hf];
                    acc[2][nt][ri] = bias[2][hf];
                    acc[3][nt][ri] = bias[3][hf];
                    float iv = sigf(gi), fv = sigf(gf), ov = sigf(go);
                    float gv = tanh_hw(gg);
                    float cn = fv * cst[nt][hf][cb] + iv * gv;
                    cst[nt][hf][cb] = cn;
                    float hv = ov * tanh_hw(cn);
                    const int d = wh * 16 + hf * 8 + g;
                    const int n = nt * 8 + tig * 2 + cb;        // local node 0..31
                    if (u < DEG - 1) {
                        __half hh = __float2half_rn(hv);
                        __half hl = __float2half_rn(hv - __half2float(hh));
                        const int kidx = wb + (64 + (d >> 1)) * ROWW + n;
                        ((__half*)&HI[kidx])[d & 1] = hh;
                        ((__half*)&LO[kidx])[d & 1] = hl;
                    } else {
                        out[(size_t)(n0 + n) * HD + d] = hv;
                    }
                }

        // ---- convert x(u+1) -> wb src0 ----
        if (u < DEG - 1) {
            const float* xr = x + ((size_t)(n0 + lane) * DEG + (u + 1)) * HD + wh * 16;
#pragma unroll
            for (int i = 0; i < 8; ++i) {
                float2 v = *(const float2*)(xr + 2 * i);
                float v0 = (v.x == v.x) ? v.x : 0.0f;
                float v1 = (v.y == v.y) ? v.y : 0.0f;
                __half2 h2 = __floats2half2_rn(v0, v1);
                __half2 l2 = __floats2half2_rn(v0 - __half2float(__low2half(h2)),
                                               v1 - __half2float(__high2half(h2)));
                int kp = wh * 8 + i;
                HI[wb + kp * ROWW + lane] = *(uint32_t*)&h2;
                LO[wb + kp * ROWW + lane] = *(uint32_t*)&l2;
            }
        }

        // per-half barrier: halves drift independently -> tensor/MUFU phases overlap
        asm volatile("bar.sync %0, 256;" :: "r"(half + 1) : "memory");
    }
}

extern "C" void kernel_launch(void* const* d_in, const int* in_sizes, int n_in,
                              void* d_out, int out_size) {
    // metadata order: x, index, W_ih, W_hh, b_ih, b_hh, dim_size
    const float* x   = (const float*)d_in[0];
    const float* Wih = (const float*)d_in[2];
    const float* Whh = (const float*)d_in[3];
    const float* bih = (const float*)d_in[4];
    const float* bhh = (const float*)d_in[5];
    float* out = (float*)d_out;

    prep_w<<<64, 256>>>(Wih, Whh);

    const int smem_bytes = SMEM_WORDS * (int)sizeof(uint32_t);   // 163840
    static bool attr_set = false;
    if (!attr_set) {
        cudaFuncSetAttribute(lstm_mma_kernel,
                             cudaFuncAttributeMaxDynamicSharedMemorySize, smem_bytes);
        attr_set = true;
    }
    lstm_mma_kernel<<<NNODES / NPC, NT, smem_bytes>>>(x, bih, bhh, out);
}

// round 16
// speedup vs baseline: 1.9732x; 1.2852x over previous
#include <cuda_runtime.h>
#include <cuda_fp16.h>
#include <cstdint>

#define HD   128
#define NPC  64            // nodes per CTA (two independent halves of 32)
#define NT   512
#define DEG  16
#define NNODES 16384

// Fragment-major weights: [mat(2: 0=ih,1=hh)][prec(2: 0=hi,1=lo)][mt(32)][kt(8)][lane(32)][8 halves]
// mt = wh*4 + t4 ; global row = t4*128 + wh*16 + r_local.
__device__ __align__(16) __half g_Wfrag[2][2][32][8][32][8];

__global__ void prep_w(const float* __restrict__ Wih, const float* __restrict__ Whh) {
    int idx = blockIdx.x * blockDim.x + threadIdx.x;      // 16384 threads
    if (idx >= 2 * 32 * 8 * 32) return;
    int lane = idx & 31;
    int kt   = (idx >> 5) & 7;
    int mt   = (idx >> 8) & 31;
    int mat  = idx >> 13;
    const float* W = mat ? Whh : Wih;
    int wh = mt >> 2, t4 = mt & 3;
    int g = lane >> 2, tig = lane & 3;
    int rb = t4 * 128 + wh * 16;
    int kb = kt * 16 + tig * 2;
    int rows[8] = {g, g, g + 8, g + 8, g, g, g + 8, g + 8};
    int cols[8] = {kb, kb + 1, kb, kb + 1, kb + 8, kb + 9, kb + 8, kb + 9};
    __half hi[8], lo[8];
#pragma unroll
    for (int i = 0; i < 8; ++i) {
        float v = W[(rb + rows[i]) * HD + cols[i]];
        __half h = __float2half_rn(v);
        hi[i] = h;
        lo[i] = __float2half_rn(v - __half2float(h));
    }
    *(uint4*)&g_Wfrag[mat][0][mt][kt][lane][0] = *(uint4*)hi;
    *(uint4*)&g_Wfrag[mat][1][mt][kt][lane][0] = *(uint4*)lo;
}

// ---- hardware tanh (MUFU.TANH), single-op activations ----
__device__ __forceinline__ float tanh_hw(float x) {
    float y;
    asm("tanh.approx.f32 %0, %1;" : "=f"(y) : "f"(x));
    return y;
}
__device__ __forceinline__ float sigf(float v) {
    return fmaf(0.5f, tanh_hw(0.5f * v), 0.5f);
}

#define MMA(acc, a, b0, b1)                                              \
    asm volatile("mma.sync.aligned.m16n8k16.row.col.f32.f16.f16.f32 "    \
                 "{%0,%1,%2,%3}, {%4,%5,%6,%7}, {%8,%9}, {%0,%1,%2,%3};" \
                 : "+f"((acc)[0]), "+f"((acc)[1]), "+f"((acc)[2]), "+f"((acc)[3]) \
                 : "r"((a).x), "r"((a).y), "r"((a).z), "r"((a).w), "r"(b0), "r"(b1))

// Per-half slabs: HI[buf(2)][src(2)][kpair(64)][ROWW]. (No LO slabs — act_lo term dropped.)
// ROWW = 32 nodes + 8 pad -> LDS pattern tig*40+g covers banks 0..31 conflict-free.
#define ROWW 40
#define SLAB (2 * 64 * ROWW)     // words per buffer (both srcs) = 5120
#define HALFW (2 * SLAB)         // 2 bufs = 10240 words per half
#define SMEM_WORDS (2 * HALFW)   // 20480 words = 80 KB

__global__ __launch_bounds__(NT, 1)
void lstm_mma_kernel(const float* __restrict__ x,
                     const float* __restrict__ bih,
                     const float* __restrict__ bhh,
                     float* __restrict__ out) {
    extern __shared__ uint32_t sm[];

    const int tid = threadIdx.x, lane = tid & 31, w = tid >> 5;
    const int half = w >> 3, wh = w & 7;
    const int g = lane >> 2, tig = lane & 3;
    const int n0 = blockIdx.x * NPC + half * 32;   // first node of this half

    uint32_t* HI = sm + half * HALFW;              // [buf][src][64][ROWW]

    // per-thread bias regs [gate-type][row-half]
    float bias[4][2];
#pragma unroll
    for (int t = 0; t < 4; ++t)
#pragma unroll
        for (int hf = 0; hf < 2; ++hf) {
            int d = t * 128 + wh * 16 + hf * 8 + g;
            bias[t][hf] = bih[d] + bhh[d];
        }

    float cst[4][2][2];
#pragma unroll
    for (int a = 0; a < 4; ++a)
        for (int b = 0; b < 2; ++b)
            for (int c = 0; c < 2; ++c) cst[a][b][c] = 0.0f;

    // ---- convert x(0) into buf 0, src 0 (warp w: dims wh*16..+16, node = lane) ----
    {
        const float* xr = x + ((size_t)(n0 + lane) * DEG + 0) * HD + wh * 16;
#pragma unroll
        for (int i = 0; i < 8; ++i) {
            float2 v = *(const float2*)(xr + 2 * i);
            float v0 = (v.x == v.x) ? v.x : 0.0f;
            float v1 = (v.y == v.y) ? v.y : 0.0f;
            __half2 h2 = __floats2half2_rn(v0, v1);
            HI[(wh * 8 + i) * ROWW + lane] = *(uint32_t*)&h2;
        }
    }
    __syncthreads();   // one full sync; afterwards halves run on their own barriers

    // accumulators pre-initialized with bias
    float acc[4][4][4];
#pragma unroll
    for (int t = 0; t < 4; ++t)
#pragma unroll
        for (int nt = 0; nt < 4; ++nt)
#pragma unroll
            for (int ri = 0; ri < 4; ++ri) acc[t][nt][ri] = bias[t][ri >> 1];

#pragma unroll 1
    for (int u = 0; u < DEG; ++u) {
        const int rb = (u & 1) * SLAB;          // GEMM reads this buffer
        const int wb = ((u + 1) & 1) * SLAB;    // epi/convert write this buffer

        // ---- GEMM: src 0 = x (Wih), src 1 = h (Whh); terms: W_hi*act + W_lo*act ----
#pragma unroll 1
        for (int src = 0; src < 2; ++src) {
            if (src == 1 && u == 0) break;
#pragma unroll 1
            for (int kt = 0; kt < 8; ++kt) {
                const int bidx = rb + (src * 64 + kt * 8 + tig) * ROWW + g;
                uint4 ah[4], al[4];
#pragma unroll
                for (int t = 0; t < 4; ++t) {
                    ah[t] = __ldg((const uint4*)&g_Wfrag[src][0][wh * 4 + t][kt][lane][0]);
                    al[t] = __ldg((const uint4*)&g_Wfrag[src][1][wh * 4 + t][kt][lane][0]);
                }
#pragma unroll
                for (int nt = 0; nt < 4; ++nt) {
                    uint32_t bh0 = HI[bidx + nt * 8];
                    uint32_t bh1 = HI[bidx + 4 * ROWW + nt * 8];
#pragma unroll
                    for (int t = 0; t < 4; ++t) MMA(acc[t][nt], ah[t], bh0, bh1);
#pragma unroll
                    for (int t = 0; t < 4; ++t) MMA(acc[t][nt], al[t], bh0, bh1);
                }
            }
        }

        // ---- epilogue: cell update (bias already inside acc); reset acc to bias ----
#pragma unroll
        for (int nt = 0; nt < 4; ++nt)
#pragma unroll
            for (int hf = 0; hf < 2; ++hf)
#pragma unroll
                for (int cb = 0; cb < 2; ++cb) {
                    const int ri = hf * 2 + cb;
                    float gi = acc[0][nt][ri];
                    float gf = acc[1][nt][ri];
                    float gg = acc[2][nt][ri];
                    float go = acc[3][nt][ri];
                    acc[0][nt][ri] = bias[0][hf];
                    acc[1][nt][ri] = bias[1][hf];
                    acc[2][nt][ri] = bias[2][hf];
                    acc[3][nt][ri] = bias[3][hf];
                    float iv = sigf(gi), fv = sigf(gf), ov = sigf(go);
                    float gv = tanh_hw(gg);
                    float cn = fv * cst[nt][hf][cb] + iv * gv;
                    cst[nt][hf][cb] = cn;
                    float hv = ov * tanh_hw(cn);
                    const int d = wh * 16 + hf * 8 + g;
                    const int n = nt * 8 + tig * 2 + cb;        // local node 0..31
                    if (u < DEG - 1) {
                        __half hh = __float2half_rn(hv);
                        const int kidx = wb + (64 + (d >> 1)) * ROWW + n;
                        ((__half*)&HI[kidx])[d & 1] = hh;
                    } else {
                        out[(size_t)(n0 + n) * HD + d] = hv;
                    }
                }

        // ---- convert x(u+1) -> wb src0 ----
        if (u < DEG - 1) {
            const float* xr = x + ((size_t)(n0 + lane) * DEG + (u + 1)) * HD + wh * 16;
#pragma unroll
            for (int i = 0; i < 8; ++i) {
                float2 v = *(const float2*)(xr + 2 * i);
                float v0 = (v.x == v.x) ? v.x : 0.0f;
                float v1 = (v.y == v.y) ? v.y : 0.0f;
                __half2 h2 = __floats2half2_rn(v0, v1);
                HI[wb + (wh * 8 + i) * ROWW + lane] = *(uint32_t*)&h2;
            }
        }

        // per-half barrier: halves drift independently -> tensor/MUFU phases overlap
        asm volatile("bar.sync %0, 256;" :: "r"(half + 1) : "memory");
    }
}

extern "C" void kernel_launch(void* const* d_in, const int* in_sizes, int n_in,
                              void* d_out, int out_size) {
    // metadata order: x, index, W_ih, W_hh, b_ih, b_hh, dim_size
    const float* x   = (const float*)d_in[0];
    const float* Wih = (const float*)d_in[2];
    const float* Whh = (const float*)d_in[3];
    const float* bih = (const float*)d_in[4];
    const float* bhh = (const float*)d_in[5];
    float* out = (float*)d_out;

    prep_w<<<64, 256>>>(Wih, Whh);

    const int smem_bytes = SMEM_WORDS * (int)sizeof(uint32_t);   // 81920
    static bool attr_set = false;
    if (!attr_set) {
        cudaFuncSetAttribute(lstm_mma_kernel,
                             cudaFuncAttributeMaxDynamicSharedMemorySize, smem_bytes);
        attr_set = true;
    }
    lstm_mma_kernel<<<NNODES / NPC, NT, smem_bytes>>>(x, bih, bhh, out);
}

// round 17
// speedup vs baseline: 2.7561x; 1.3967x over previous
#include <cuda_runtime.h>
#include <cuda_fp16.h>
#include <cstdint>

#define HD   128
#define NPC  64            // nodes per CTA (two independent halves of 32)
#define NT   512
#define DEG  16
#define NNODES 16384

// Fragment-major weights (fp16, single precision term):
// [mat(2: 0=ih,1=hh)][mt(32)][kt(8)][lane(32)][8 halves]
// mt = wh*4 + t4 ; global row = t4*128 + wh*16 + r_local.
__device__ __align__(16) __half g_Wfrag[2][32][8][32][8];

__global__ void prep_w(const float* __restrict__ Wih, const float* __restrict__ Whh) {
    int idx = blockIdx.x * blockDim.x + threadIdx.x;      // 16384 threads
    if (idx >= 2 * 32 * 8 * 32) return;
    int lane = idx & 31;
    int kt   = (idx >> 5) & 7;
    int mt   = (idx >> 8) & 31;
    int mat  = idx >> 13;
    const float* W = mat ? Whh : Wih;
    int wh = mt >> 2, t4 = mt & 3;
    int g = lane >> 2, tig = lane & 3;
    int rb = t4 * 128 + wh * 16;
    int kb = kt * 16 + tig * 2;
    int rows[8] = {g, g, g + 8, g + 8, g, g, g + 8, g + 8};
    int cols[8] = {kb, kb + 1, kb, kb + 1, kb + 8, kb + 9, kb + 8, kb + 9};
    __half hi[8];
#pragma unroll
    for (int i = 0; i < 8; ++i)
        hi[i] = __float2half_rn(W[(rb + rows[i]) * HD + cols[i]]);
    *(uint4*)&g_Wfrag[mat][mt][kt][lane][0] = *(uint4*)hi;
}

// ---- hardware tanh (MUFU.TANH), single-op activations ----
__device__ __forceinline__ float tanh_hw(float x) {
    float y;
    asm("tanh.approx.f32 %0, %1;" : "=f"(y) : "f"(x));
    return y;
}
__device__ __forceinline__ float sigf(float v) {
    return fmaf(0.5f, tanh_hw(0.5f * v), 0.5f);
}

#define MMA(acc, a, b0, b1)                                              \
    asm volatile("mma.sync.aligned.m16n8k16.row.col.f32.f16.f16.f32 "    \
                 "{%0,%1,%2,%3}, {%4,%5,%6,%7}, {%8,%9}, {%0,%1,%2,%3};" \
                 : "+f"((acc)[0]), "+f"((acc)[1]), "+f"((acc)[2]), "+f"((acc)[3]) \
                 : "r"((a).x), "r"((a).y), "r"((a).z), "r"((a).w), "r"(b0), "r"(b1))

// Per-half slabs: HI[buf(2)][src(2)][kpair(64)][ROWW].
// ROWW = 32 nodes + 8 pad -> LDS pattern tig*40+g covers banks 0..31 conflict-free.
#define ROWW 40
#define SLAB (2 * 64 * ROWW)     // words per buffer (both srcs) = 5120
#define HALFW (2 * SLAB)         // 2 bufs = 10240 words per half
#define SMEM_WORDS (2 * HALFW)   // 20480 words = 80 KB

__global__ __launch_bounds__(NT, 1)
void lstm_mma_kernel(const float* __restrict__ x,
                     const float* __restrict__ bih,
                     const float* __restrict__ bhh,
                     float* __restrict__ out) {
    extern __shared__ uint32_t sm[];

    const int tid = threadIdx.x, lane = tid & 31, w = tid >> 5;
    const int half = w >> 3, wh = w & 7;
    const int g = lane >> 2, tig = lane & 3;
    const int n0 = blockIdx.x * NPC + half * 32;   // first node of this half

    uint32_t* HI = sm + half * HALFW;              // [buf][src][64][ROWW]

    // per-thread bias regs [gate-type][row-half]
    float bias[4][2];
#pragma unroll
    for (int t = 0; t < 4; ++t)
#pragma unroll
        for (int hf = 0; hf < 2; ++hf) {
            int d = t * 128 + wh * 16 + hf * 8 + g;
            bias[t][hf] = bih[d] + bhh[d];
        }

    float cst[4][2][2];
#pragma unroll
    for (int a = 0; a < 4; ++a)
        for (int b = 0; b < 2; ++b)
            for (int c = 0; c < 2; ++c) cst[a][b][c] = 0.0f;

    // ---- convert x(0) into buf 0, src 0 (warp w: dims wh*16..+16, node = lane) ----
    {
        const float* xr = x + ((size_t)(n0 + lane) * DEG + 0) * HD + wh * 16;
#pragma unroll
        for (int i = 0; i < 8; ++i) {
            float2 v = *(const float2*)(xr + 2 * i);
            float v0 = (v.x == v.x) ? v.x : 0.0f;
            float v1 = (v.y == v.y) ? v.y : 0.0f;
            __half2 h2 = __floats2half2_rn(v0, v1);
            HI[(wh * 8 + i) * ROWW + lane] = *(uint32_t*)&h2;
        }
    }
    __syncthreads();   // one full sync; afterwards halves run on their own barriers

    // accumulators pre-initialized with bias
    float acc[4][4][4];
#pragma unroll
    for (int t = 0; t < 4; ++t)
#pragma unroll
        for (int nt = 0; nt < 4; ++nt)
#pragma unroll
            for (int ri = 0; ri < 4; ++ri) acc[t][nt][ri] = bias[t][ri >> 1];

#pragma unroll 1
    for (int u = 0; u < DEG; ++u) {
        const int rb = (u & 1) * SLAB;          // GEMM reads this buffer
        const int wb = ((u + 1) & 1) * SLAB;    // epi/convert write this buffer

        // ---- GEMM: src 0 = x (Wih), src 1 = h (Whh); single fp16 term ----
#pragma unroll 1
        for (int src = 0; src < 2; ++src) {
            if (src == 1 && u == 0) break;
#pragma unroll 1
            for (int kt = 0; kt < 8; ++kt) {
                const int bidx = rb + (src * 64 + kt * 8 + tig) * ROWW + g;
                uint4 ah[4];
#pragma unroll
                for (int t = 0; t < 4; ++t)
                    ah[t] = __ldg((const uint4*)&g_Wfrag[src][wh * 4 + t][kt][lane][0]);
#pragma unroll
                for (int nt = 0; nt < 4; ++nt) {
                    uint32_t bh0 = HI[bidx + nt * 8];
                    uint32_t bh1 = HI[bidx + 4 * ROWW + nt * 8];
#pragma unroll
                    for (int t = 0; t < 4; ++t) MMA(acc[t][nt], ah[t], bh0, bh1);
                }
            }
        }

        // ---- epilogue: cell update (bias already inside acc); reset acc to bias ----
#pragma unroll
        for (int nt = 0; nt < 4; ++nt)
#pragma unroll
            for (int hf = 0; hf < 2; ++hf)
#pragma unroll
                for (int cb = 0; cb < 2; ++cb) {
                    const int ri = hf * 2 + cb;
                    float gi = acc[0][nt][ri];
                    float gf = acc[1][nt][ri];
                    float gg = acc[2][nt][ri];
                    float go = acc[3][nt][ri];
                    acc[0][nt][ri] = bias[0][hf];
                    acc[1][nt][ri] = bias[1][hf];
                    acc[2][nt][ri] = bias[2][hf];
                    acc[3][nt][ri] = bias[3][hf];
                    float iv = sigf(gi), fv = sigf(gf), ov = sigf(go);
                    float gv = tanh_hw(gg);
                    float cn = fv * cst[nt][hf][cb] + iv * gv;
                    cst[nt][hf][cb] = cn;
                    float hv = ov * tanh_hw(cn);
                    const int d = wh * 16 + hf * 8 + g;
                    const int n = nt * 8 + tig * 2 + cb;        // local node 0..31
                    if (u < DEG - 1) {
                        __half hh = __float2half_rn(hv);
                        const int kidx = wb + (64 + (d >> 1)) * ROWW + n;
                        ((__half*)&HI[kidx])[d & 1] = hh;
                    } else {
                        out[(size_t)(n0 + n) * HD + d] = hv;
                    }
                }

        // ---- convert x(u+1) -> wb src0 ----
        if (u < DEG - 1) {
            const float* xr = x + ((size_t)(n0 + lane) * DEG + (u + 1)) * HD + wh * 16;
#pragma unroll
            for (int i = 0; i < 8; ++i) {
                float2 v = *(const float2*)(xr + 2 * i);
                float v0 = (v.x == v.x) ? v.x : 0.0f;
                float v1 = (v.y == v.y) ? v.y : 0.0f;
                __half2 h2 = __floats2half2_rn(v0, v1);
                HI[wb + (wh * 8 + i) * ROWW + lane] = *(uint32_t*)&h2;
            }
        }

        // per-half barrier: halves drift independently -> tensor/MUFU phases overlap
        asm volatile("bar.sync %0, 256;" :: "r"(half + 1) : "memory");
    }
}

extern "C" void kernel_launch(void* const* d_in, const int* in_sizes, int n_in,
                              void* d_out, int out_size) {
    // metadata order: x, index, W_ih, W_hh, b_ih, b_hh, dim_size
    const float* x   = (const float*)d_in[0];
    const float* Wih = (const float*)d_in[2];
    const float* Whh = (const float*)d_in[3];
    const float* bih = (const float*)d_in[4];
    const float* bhh = (const float*)d_in[5];
    float* out = (float*)d_out;

    prep_w<<<64, 256>>>(Wih, Whh);

    const int smem_bytes = SMEM_WORDS * (int)sizeof(uint32_t);   // 81920
    static bool attr_set = false;
    if (!attr_set) {
        cudaFuncSetAttribute(lstm_mma_kernel,
                             cudaFuncAttributeMaxDynamicSharedMemorySize, smem_bytes);
        attr_set = true;
    }
    lstm_mma_kernel<<<NNODES / NPC, NT, smem_bytes>>>(x, bih, bhh, out);
}